// round 1
// baseline (speedup 1.0000x reference)
#include <cuda_runtime.h>

#define THREADS 256
#define BT 32          // batch elements per block
#define T_STEPS 20
#define BETA 0.9f
#define THR 1.0f

// shared-memory layout (floats)
#define OFF_W1   0                  // [16][128]       2048
#define OFF_W2   (OFF_W1 + 2048)    // [128][132]     16896 (padded rows)
#define OFF_W3   (OFF_W2 + 16896)   // [64][132]       8448
#define OFF_W4   (OFF_W3 + 8448)    // [10][68]         680
#define OFF_XS   (OFF_W4 + 680)     // [32][16]         512
#define OFF_S1   (OFF_XS + 512)     // [32][128]       4096
#define OFF_S2   (OFF_S1 + 4096)    // [32][128]       4096
#define OFF_S3   (OFF_S2 + 4096)    // [32][64]        2048
#define SMEM_FLOATS (OFF_S3 + 2048) // 38824
#define SMEM_BYTES (SMEM_FLOATS * 4)

__global__ void __launch_bounds__(THREADS, 1)
snn_kernel(const float* __restrict__ x,
           const float* __restrict__ w1,
           const float* __restrict__ w2,
           const float* __restrict__ w3,
           const float* __restrict__ w4,
           float* __restrict__ out,
           int Btot)
{
    extern __shared__ float sm[];
    float* w1t = sm + OFF_W1;   // w1t[f*128 + j] = w1[j][f]
    float* w2p = sm + OFF_W2;   // w2p[j*132 + i] = w2[j][i]
    float* w3p = sm + OFF_W3;   // w3p[n*132 + i] = w3[n][i]
    float* w4p = sm + OFF_W4;   // w4p[n*68  + i] = w4[n][i]
    float* xs  = sm + OFF_XS;   // xs[bb*16 + f]
    float* s1  = sm + OFF_S1;   // s1[bb*128 + j]
    float* s2  = sm + OFF_S2;   // s2[bb*128 + j]
    float* s3  = sm + OFF_S3;   // s3[bb*64  + n]

    const int tid = threadIdx.x;
    const int b0  = blockIdx.x * BT;

    // ---- load weights into shared (once per block) ----
    for (int idx = tid; idx < 128 * 16; idx += THREADS) {
        int j = idx >> 4, f = idx & 15;
        w1t[f * 128 + j] = w1[idx];
    }
    for (int idx = tid; idx < 128 * 128; idx += THREADS) {
        int j = idx >> 7, i = idx & 127;
        w2p[j * 132 + i] = w2[idx];
    }
    for (int idx = tid; idx < 64 * 128; idx += THREADS) {
        int n = idx >> 7, i = idx & 127;
        w3p[n * 132 + i] = w3[idx];
    }
    for (int idx = tid; idx < 10 * 64; idx += THREADS) {
        int n = idx >> 6, i = idx & 63;
        w4p[n * 68 + i] = w4[idx];
    }

    // ---- per-thread roles ----
    const int j12  = tid & 127;        // L1/L2 neuron
    const int bb12 = (tid >> 7) * 16;  // batch half
    const int n3   = tid & 63;         // L3 neuron
    const int bb3  = (tid >> 6) * 8;   // batch quarter
    const int n4   = tid & 15;         // L4 neuron (valid if < 10)
    const int bb4  = (tid >> 4) * 2;   // batch pair

    // ---- membrane state in registers ----
    float mem1[16], mem2[16], mem3[8], mem4[2];
#pragma unroll
    for (int k = 0; k < 16; k++) { mem1[k] = 0.f; mem2[k] = 0.f; }
#pragma unroll
    for (int k = 0; k < 8; k++)  mem3[k] = 0.f;
    mem4[0] = 0.f; mem4[1] = 0.f;

    __syncthreads();

    for (int t = 0; t < T_STEPS; t++) {
        // ---- load x tile (32 batches x 16 features), coalesced ----
        const float* xg = x + ((size_t)t * (size_t)Btot + (size_t)b0) * 16;
        for (int idx = tid; idx < BT * 16; idx += THREADS)
            xs[idx] = xg[idx];
        __syncthreads();

        // ---- layer 1: cur = x @ w1^T (K=16) ----
        {
            float cur[16];
#pragma unroll
            for (int k = 0; k < 16; k++) cur[k] = 0.f;
#pragma unroll
            for (int f = 0; f < 16; f++) {
                float w = w1t[f * 128 + j12];
#pragma unroll
                for (int k = 0; k < 16; k++)
                    cur[k] = fmaf(xs[(bb12 + k) * 16 + f], w, cur[k]);
            }
#pragma unroll
            for (int k = 0; k < 16; k++) {
                float m = mem1[k];
                float reset = (m > THR) ? 1.0f : 0.0f;
                m = fmaf(BETA, m, cur[k]) - reset;
                mem1[k] = m;
                s1[(bb12 + k) * 128 + j12] = (m > THR) ? 1.0f : 0.0f;
            }
        }
        __syncthreads();

        // ---- layer 2: cur = spk1 @ w2^T (K=128) ----
        {
            float cur[16];
#pragma unroll
            for (int k = 0; k < 16; k++) cur[k] = 0.f;
            const float* wrow = &w2p[j12 * 132];
            for (int i = 0; i < 128; i += 4) {
                float4 w = *(const float4*)&wrow[i];
#pragma unroll
                for (int k = 0; k < 16; k++) {
                    float4 s = *(const float4*)&s1[(bb12 + k) * 128 + i];
                    float c = cur[k];
                    c = fmaf(s.x, w.x, c);
                    c = fmaf(s.y, w.y, c);
                    c = fmaf(s.z, w.z, c);
                    c = fmaf(s.w, w.w, c);
                    cur[k] = c;
                }
            }
#pragma unroll
            for (int k = 0; k < 16; k++) {
                float m = mem2[k];
                float reset = (m > THR) ? 1.0f : 0.0f;
                m = fmaf(BETA, m, cur[k]) - reset;
                mem2[k] = m;
                s2[(bb12 + k) * 128 + j12] = (m > THR) ? 1.0f : 0.0f;
            }
        }
        __syncthreads();

        // ---- layer 3: cur = spk2 @ w3^T (K=128, 64 neurons) ----
        {
            float cur[8];
#pragma unroll
            for (int k = 0; k < 8; k++) cur[k] = 0.f;
            const float* wrow = &w3p[n3 * 132];
            for (int i = 0; i < 128; i += 4) {
                float4 w = *(const float4*)&wrow[i];
#pragma unroll
                for (int k = 0; k < 8; k++) {
                    float4 s = *(const float4*)&s2[(bb3 + k) * 128 + i];
                    float c = cur[k];
                    c = fmaf(s.x, w.x, c);
                    c = fmaf(s.y, w.y, c);
                    c = fmaf(s.z, w.z, c);
                    c = fmaf(s.w, w.w, c);
                    cur[k] = c;
                }
            }
#pragma unroll
            for (int k = 0; k < 8; k++) {
                float m = mem3[k];
                float reset = (m > THR) ? 1.0f : 0.0f;
                m = fmaf(BETA, m, cur[k]) - reset;
                mem3[k] = m;
                s3[(bb3 + k) * 64 + n3] = (m > THR) ? 1.0f : 0.0f;
            }
        }
        __syncthreads();

        // ---- layer 4: cur = spk3 @ w4^T (K=64, 10 neurons) -> global out ----
        if (n4 < 10) {
            float cur[2];
            cur[0] = 0.f; cur[1] = 0.f;
            const float* wrow = &w4p[n4 * 68];
            for (int i = 0; i < 64; i += 4) {
                float4 w = *(const float4*)&wrow[i];
#pragma unroll
                for (int k = 0; k < 2; k++) {
                    float4 s = *(const float4*)&s3[(bb4 + k) * 64 + i];
                    float c = cur[k];
                    c = fmaf(s.x, w.x, c);
                    c = fmaf(s.y, w.y, c);
                    c = fmaf(s.z, w.z, c);
                    c = fmaf(s.w, w.w, c);
                    cur[k] = c;
                }
            }
#pragma unroll
            for (int k = 0; k < 2; k++) {
                float m = mem4[k];
                float reset = (m > THR) ? 1.0f : 0.0f;
                m = fmaf(BETA, m, cur[k]) - reset;
                mem4[k] = m;
                float spk = (m > THR) ? 1.0f : 0.0f;
                out[((size_t)t * (size_t)Btot + (size_t)(b0 + bb4 + k)) * 10 + n4] = spk;
            }
        }
        __syncthreads();
    }
}

extern "C" void kernel_launch(void* const* d_in, const int* in_sizes, int n_in,
                              void* d_out, int out_size) {
    const float* x  = (const float*)d_in[0];
    const float* w1 = (const float*)d_in[1];
    const float* w2 = (const float*)d_in[2];
    const float* w3 = (const float*)d_in[3];
    const float* w4 = (const float*)d_in[4];
    float* out = (float*)d_out;

    const int Btot = in_sizes[0] / (T_STEPS * 16);  // 65536
    const int grid = Btot / BT;                     // 2048

    cudaFuncSetAttribute(snn_kernel,
                         cudaFuncAttributeMaxDynamicSharedMemorySize,
                         SMEM_BYTES);
    snn_kernel<<<grid, THREADS, SMEM_BYTES>>>(x, w1, w2, w3, w4, out, Btot);
}

// round 2
// speedup vs baseline: 1.4255x; 1.4255x over previous
#include <cuda_runtime.h>

#define THREADS 256
#define T_STEPS 20
#define BETA 0.9f
#define THR 1.0f

typedef unsigned long long u64;

// ---- smem layout (units: floats unless noted) ----
#define P_W1 20      // w1 row pitch (floats)
#define P_W2 132     // w2 row pitch (floats)
#define P_W3 132     // w3 row pitch (floats)
#define P_W4 66      // w4pack row pitch (u64)
#define P_XP 36      // xp row pitch (floats)
#define P_S12 130    // s1p/s2p row pitch (u64)
#define P_S3 66      // s3p row pitch (u64)

#define OFF_W1 0
#define OFF_W2 (OFF_W1 + 128*P_W1)        // 2560
#define OFF_W3 (OFF_W2 + 128*P_W2)        // 19456
#define OFF_W4 (OFF_W3 + 64*P_W3)         // 27904
#define OFF_XP (OFF_W4 + 8*P_W4*2)        // 28960
#define OFF_S1 (OFF_XP + 16*P_XP)         // 29536
#define OFF_S2 (OFF_S1 + 16*P_S12*2)      // 33696
#define OFF_S3 (OFF_S2 + 16*P_S12*2)      // 37856
#define SMEM_FLOATS (OFF_S3 + 16*P_S3*2)  // 39968
#define SMEM_BYTES (SMEM_FLOATS*4)        // 159872

// ---- packed fp32 helpers ----
__device__ __forceinline__ u64 dup2(float w) {
    u64 r; asm("mov.b64 %0, {%1, %1};" : "=l"(r) : "f"(w)); return r;
}
__device__ __forceinline__ void fma2(u64 &d, u64 a, u64 b) {
    asm("fma.rn.f32x2 %0, %1, %2, %0;" : "+l"(d) : "l"(a), "l"(b));
}
__device__ __forceinline__ void unpack2(u64 v, float &lo, float &hi) {
    asm("mov.b64 {%0, %1}, %2;" : "=f"(lo), "=f"(hi) : "l"(v));
}
__device__ __forceinline__ u64 pack2(float lo, float hi) {
    u64 r; asm("mov.b64 %0, {%1, %2};" : "=l"(r) : "f"(lo), "f"(hi)); return r;
}

// LIF update on a packed pair; updates mem in place, returns packed spikes.
__device__ __forceinline__ u64 lif2(u64 &mem, u64 cur) {
    float m0, m1, c0, c1;
    unpack2(mem, m0, m1);
    unpack2(cur, c0, c1);
    float r0 = (m0 > THR) ? 1.0f : 0.0f;
    float r1 = (m1 > THR) ? 1.0f : 0.0f;
    m0 = fmaf(BETA, m0, c0) - r0;
    m1 = fmaf(BETA, m1, c1) - r1;
    float s0 = (m0 > THR) ? 1.0f : 0.0f;
    float s1 = (m1 > THR) ? 1.0f : 0.0f;
    mem = pack2(m0, m1);
    return pack2(s0, s1);
}

__global__ void __launch_bounds__(THREADS, 1)
snn_kernel(const float* __restrict__ x,
           const float* __restrict__ w1,
           const float* __restrict__ w2,
           const float* __restrict__ w3,
           const float* __restrict__ w4,
           float* __restrict__ out,
           int Btot)
{
    extern __shared__ float smf[];
    u64* smu = reinterpret_cast<u64*>(smf);

    const int tid  = threadIdx.x;
    const int warp = tid >> 5;
    const int lane = tid & 31;
    const int b0   = blockIdx.x * 32;

    // ---- stage weights into shared ----
    for (int idx = tid; idx < 128 * 16; idx += THREADS) {
        int j = idx >> 4, f = idx & 15;
        smf[OFF_W1 + j * P_W1 + f] = w1[idx];
    }
    for (int idx = tid; idx < 128 * 128; idx += THREADS)
        smf[OFF_W2 + (idx >> 7) * P_W2 + (idx & 127)] = w2[idx];
    for (int idx = tid; idx < 64 * 128; idx += THREADS)
        smf[OFF_W3 + (idx >> 7) * P_W3 + (idx & 127)] = w3[idx];
    for (int idx = tid; idx < 8 * 64 * 2; idx += THREADS) {
        int np = idx >> 7, r = idx & 127;
        int i = r >> 1, e = r & 1;
        int n = 2 * np + e;
        smf[OFF_W4 + np * (P_W4 * 2) + 2 * i + e] = (n < 10) ? w4[n * 64 + i] : 0.0f;
    }

    // ---- per-thread roles ----
    // L1/L2: warp covers neurons [16w,16w+16), all 32 batches.
    //   lane: g = lane&7 -> neurons {16w+g, 16w+g+8}; pg = lane>>3 -> pairs {pg+4k}
    const int g  = lane & 7;
    const int pg = lane >> 3;
    const int j12a = warp * 16 + g;     // first neuron (second = +8)
    // L3: warp covers neurons [8w,8w+8).
    //   lane: ng3 = lane&3 -> neurons {8w+ng3, 8w+ng3+4}; pg3 = lane>>2 -> pairs {pg3, pg3+8}
    const int ng3 = lane & 3;
    const int pg3 = lane >> 2;
    const int j3a = warp * 8 + ng3;
    // L4: tid<80: pair = tid&15, np = tid>>4 (neuron pair 2np,2np+1)
    const int pr4 = tid & 15;
    const int np4 = tid >> 4;

    // weight row pointers
    const float* w1a = smf + OFF_W1 + j12a * P_W1;
    const float* w1b = w1a + 8 * P_W1;
    const float* w2a = smf + OFF_W2 + j12a * P_W2;
    const float* w2b = w2a + 8 * P_W2;
    const float* w3a = smf + OFF_W3 + j3a * P_W3;
    const float* w3b = w3a + 4 * P_W3;
    const u64*   w4r = smu + OFF_W4 / 2 + np4 * P_W4;

    const u64* s1rd[4];
    const u64* xprd[4];
#pragma unroll
    for (int k = 0; k < 4; k++) {
        s1rd[k] = smu + OFF_S1 / 2 + (pg + 4 * k) * P_S12;
        xprd[k] = smu + OFF_XP / 2 + (pg + 4 * k) * (P_XP / 2);
    }
    const u64* s2r0 = smu + OFF_S2 / 2 + pg3 * P_S12;
    const u64* s2r1 = s2r0 + 8 * P_S12;
    const u64* s3r4 = smu + OFF_S3 / 2 + pr4 * P_S3;

    u64* s1w = smu + OFF_S1 / 2;
    u64* s2w = smu + OFF_S2 / 2;
    u64* s3w = smu + OFF_S3 / 2;

    // ---- membrane state (packed pairs) ----
    u64 mem1[2][4], mem2[2][4], mem3[2][2], mem4[2];
#pragma unroll
    for (int k = 0; k < 4; k++) {
        mem1[0][k] = 0ull; mem1[1][k] = 0ull;
        mem2[0][k] = 0ull; mem2[1][k] = 0ull;
    }
    mem3[0][0] = mem3[0][1] = mem3[1][0] = mem3[1][1] = 0ull;
    mem4[0] = mem4[1] = 0ull;

    __syncthreads();

    for (int t = 0; t < T_STEPS; t++) {
        // ---- stage x tile, packed by batch pair: xp[p][2f+e] ----
        const float* xg = x + ((size_t)t * (size_t)Btot + (size_t)b0) * 16;
#pragma unroll
        for (int r = 0; r < 2; r++) {
            int idx = tid + r * 256;
            int b = idx >> 4, f = idx & 15;
            smf[OFF_XP + (b >> 1) * P_XP + 2 * f + (b & 1)] = xg[idx];
        }
        __syncthreads();

        // ---- layer 1: K=16 ----
        {
            u64 acc[2][4];
#pragma unroll
            for (int k = 0; k < 4; k++) { acc[0][k] = 0ull; acc[1][k] = 0ull; }
#pragma unroll
            for (int f = 0; f < 16; f += 4) {
                float4 wa = *(const float4*)(w1a + f);
                float4 wb = *(const float4*)(w1b + f);
                u64 a0 = dup2(wa.x), a1 = dup2(wa.y), a2 = dup2(wa.z), a3 = dup2(wa.w);
                u64 b0d = dup2(wb.x), b1d = dup2(wb.y), b2d = dup2(wb.z), b3d = dup2(wb.w);
#pragma unroll
                for (int k = 0; k < 4; k++) {
                    ulonglong2 xA = *(const ulonglong2*)(xprd[k] + f);
                    ulonglong2 xB = *(const ulonglong2*)(xprd[k] + f + 2);
                    fma2(acc[0][k], xA.x, a0);  fma2(acc[0][k], xA.y, a1);
                    fma2(acc[0][k], xB.x, a2);  fma2(acc[0][k], xB.y, a3);
                    fma2(acc[1][k], xA.x, b0d); fma2(acc[1][k], xA.y, b1d);
                    fma2(acc[1][k], xB.x, b2d); fma2(acc[1][k], xB.y, b3d);
                }
            }
#pragma unroll
            for (int k = 0; k < 4; k++) {
                int p = pg + 4 * k;
                u64 sp0 = lif2(mem1[0][k], acc[0][k]);
                u64 sp1 = lif2(mem1[1][k], acc[1][k]);
                s1w[p * P_S12 + j12a]     = sp0;
                s1w[p * P_S12 + j12a + 8] = sp1;
            }
        }
        __syncthreads();

        // ---- layer 2: K=128 ----
        {
            u64 acc[2][4];
#pragma unroll
            for (int k = 0; k < 4; k++) { acc[0][k] = 0ull; acc[1][k] = 0ull; }
#pragma unroll 4
            for (int i = 0; i < 128; i += 4) {
                float4 wa = *(const float4*)(w2a + i);
                float4 wb = *(const float4*)(w2b + i);
                u64 a0 = dup2(wa.x), a1 = dup2(wa.y), a2 = dup2(wa.z), a3 = dup2(wa.w);
                u64 b0d = dup2(wb.x), b1d = dup2(wb.y), b2d = dup2(wb.z), b3d = dup2(wb.w);
#pragma unroll
                for (int k = 0; k < 4; k++) {
                    ulonglong2 sA = *(const ulonglong2*)(s1rd[k] + i);
                    ulonglong2 sB = *(const ulonglong2*)(s1rd[k] + i + 2);
                    fma2(acc[0][k], sA.x, a0);  fma2(acc[0][k], sA.y, a1);
                    fma2(acc[0][k], sB.x, a2);  fma2(acc[0][k], sB.y, a3);
                    fma2(acc[1][k], sA.x, b0d); fma2(acc[1][k], sA.y, b1d);
                    fma2(acc[1][k], sB.x, b2d); fma2(acc[1][k], sB.y, b3d);
                }
            }
#pragma unroll
            for (int k = 0; k < 4; k++) {
                int p = pg + 4 * k;
                u64 sp0 = lif2(mem2[0][k], acc[0][k]);
                u64 sp1 = lif2(mem2[1][k], acc[1][k]);
                s2w[p * P_S12 + j12a]     = sp0;
                s2w[p * P_S12 + j12a + 8] = sp1;
            }
        }
        __syncthreads();

        // ---- layer 3: K=128, 64 neurons ----
        {
            u64 acc[2][2];
            acc[0][0] = acc[0][1] = acc[1][0] = acc[1][1] = 0ull;
#pragma unroll 4
            for (int i = 0; i < 128; i += 4) {
                float4 wa = *(const float4*)(w3a + i);
                float4 wb = *(const float4*)(w3b + i);
                u64 a0 = dup2(wa.x), a1 = dup2(wa.y), a2 = dup2(wa.z), a3 = dup2(wa.w);
                u64 b0d = dup2(wb.x), b1d = dup2(wb.y), b2d = dup2(wb.z), b3d = dup2(wb.w);

                ulonglong2 sA0 = *(const ulonglong2*)(s2r0 + i);
                ulonglong2 sB0 = *(const ulonglong2*)(s2r0 + i + 2);
                fma2(acc[0][0], sA0.x, a0);  fma2(acc[0][0], sA0.y, a1);
                fma2(acc[0][0], sB0.x, a2);  fma2(acc[0][0], sB0.y, a3);
                fma2(acc[1][0], sA0.x, b0d); fma2(acc[1][0], sA0.y, b1d);
                fma2(acc[1][0], sB0.x, b2d); fma2(acc[1][0], sB0.y, b3d);

                ulonglong2 sA1 = *(const ulonglong2*)(s2r1 + i);
                ulonglong2 sB1 = *(const ulonglong2*)(s2r1 + i + 2);
                fma2(acc[0][1], sA1.x, a0);  fma2(acc[0][1], sA1.y, a1);
                fma2(acc[0][1], sB1.x, a2);  fma2(acc[0][1], sB1.y, a3);
                fma2(acc[1][1], sA1.x, b0d); fma2(acc[1][1], sA1.y, b1d);
                fma2(acc[1][1], sB1.x, b2d); fma2(acc[1][1], sB1.y, b3d);
            }
#pragma unroll
            for (int k = 0; k < 2; k++) {
                int p = pg3 + 8 * k;
                u64 sp0 = lif2(mem3[0][k], acc[0][k]);
                u64 sp1 = lif2(mem3[1][k], acc[1][k]);
                s3w[p * P_S3 + j3a]     = sp0;
                s3w[p * P_S3 + j3a + 4] = sp1;
            }
        }
        __syncthreads();

        // ---- layer 4: K=64, 10 neurons (packed by neuron pair) ----
        if (tid < 80) {
            u64 aB0 = 0ull, aB1 = 0ull;
#pragma unroll 4
            for (int i = 0; i < 64; i += 2) {
                ulonglong2 wp = *(const ulonglong2*)(w4r + i);   // {w(n0,i),w(n1,i)},{w(n0,i+1),w(n1,i+1)}
                ulonglong2 sp = *(const ulonglong2*)(s3r4 + i);  // {s(b0,i),s(b1,i)},{...,i+1}
                float lo, hi;
                unpack2(sp.x, lo, hi);
                u64 d0 = dup2(lo), d1 = dup2(hi);
                fma2(aB0, d0, wp.x); fma2(aB1, d1, wp.x);
                unpack2(sp.y, lo, hi);
                u64 e0 = dup2(lo), e1 = dup2(hi);
                fma2(aB0, e0, wp.y); fma2(aB1, e1, wp.y);
            }
            u64 spB0 = lif2(mem4[0], aB0);  // spikes for (2np,2np+1) @ batch b0+2pr
            u64 spB1 = lif2(mem4[1], aB1);  // @ batch b0+2pr+1
            size_t ob = ((size_t)t * (size_t)Btot + (size_t)(b0 + 2 * pr4)) * 10 + 2 * np4;
            *reinterpret_cast<u64*>(out + ob)      = spB0;
            *reinterpret_cast<u64*>(out + ob + 10) = spB1;
        }
        __syncthreads();
    }
}

extern "C" void kernel_launch(void* const* d_in, const int* in_sizes, int n_in,
                              void* d_out, int out_size) {
    const float* x  = (const float*)d_in[0];
    const float* w1 = (const float*)d_in[1];
    const float* w2 = (const float*)d_in[2];
    const float* w3 = (const float*)d_in[3];
    const float* w4 = (const float*)d_in[4];
    float* out = (float*)d_out;

    const int Btot = in_sizes[0] / (T_STEPS * 16);  // 65536
    const int grid = Btot / 32;                     // 2048

    cudaFuncSetAttribute(snn_kernel,
                         cudaFuncAttributeMaxDynamicSharedMemorySize,
                         SMEM_BYTES);
    snn_kernel<<<grid, THREADS, SMEM_BYTES>>>(x, w1, w2, w3, w4, out, Btot);
}

// round 4
// speedup vs baseline: 1.9415x; 1.3619x over previous
#include <cuda_runtime.h>

#define THREADS 256
#define T_STEPS 20
#define BETA 0.9f
#define THR 1.0f

typedef unsigned long long u64;

// ---- smem layout (float offsets) ----
// w1: 128 x 20, w2: 128 x 132, w3: 64 x 132, w4: 5 x 132 (packed neuron pairs)
// xp: 32 pairs x 36, s1/s2: 32 pairs x 260 (130 u64), s3: 32 pairs x 132 (66 u64)
#define OFF_W1 0
#define OFF_W2 2560
#define OFF_W3 19456
#define OFF_W4 27904
#define OFF_XP 28564
#define OFF_S1 29716
#define OFF_S2 38036
#define OFF_S3 46356
#define SMEM_FLOATS 50580
#define SMEM_BYTES (SMEM_FLOATS * 4)   // 202320 B

// ---- packed fp32 helpers ----
__device__ __forceinline__ u64 dup2(float w) {
    u64 r; asm("mov.b64 %0, {%1, %1};" : "=l"(r) : "f"(w)); return r;
}
__device__ __forceinline__ void fma2(u64 &d, u64 a, u64 b) {
    asm("fma.rn.f32x2 %0, %1, %2, %0;" : "+l"(d) : "l"(a), "l"(b));
}
__device__ __forceinline__ void unpack2(u64 v, float &lo, float &hi) {
    asm("mov.b64 {%0, %1}, %2;" : "=f"(lo), "=f"(hi) : "l"(v));
}
__device__ __forceinline__ u64 pack2(float lo, float hi) {
    u64 r; asm("mov.b64 %0, {%1, %2};" : "=l"(r) : "f"(lo), "f"(hi)); return r;
}
__device__ __forceinline__ u64 lif2(u64 &mem, u64 cur) {
    float m0, m1, c0, c1;
    unpack2(mem, m0, m1);
    unpack2(cur, c0, c1);
    float r0 = (m0 > THR) ? 1.0f : 0.0f;
    float r1 = (m1 > THR) ? 1.0f : 0.0f;
    m0 = fmaf(BETA, m0, c0) - r0;
    m1 = fmaf(BETA, m1, c1) - r1;
    float s0 = (m0 > THR) ? 1.0f : 0.0f;
    float s1 = (m1 > THR) ? 1.0f : 0.0f;
    mem = pack2(m0, m1);
    return pack2(s0, s1);
}

__global__ void __launch_bounds__(THREADS, 1)
snn_kernel(const float* __restrict__ x,
           const float* __restrict__ w1,
           const float* __restrict__ w2,
           const float* __restrict__ w3,
           const float* __restrict__ w4,
           float* __restrict__ out,
           int Btot)
{
    extern __shared__ float smf[];
    u64* smu = reinterpret_cast<u64*>(smf);

    const int tid  = threadIdx.x;
    const int warp = tid >> 5;
    const int lane = tid & 31;
    const int b0   = blockIdx.x * 64;

    // ---- stage weights ----
    for (int idx = tid; idx < 128 * 16; idx += THREADS)
        smf[OFF_W1 + (idx >> 4) * 20 + (idx & 15)] = w1[idx];
    for (int idx = tid; idx < 128 * 128; idx += THREADS)
        smf[OFF_W2 + (idx >> 7) * 132 + (idx & 127)] = w2[idx];
    for (int idx = tid; idx < 64 * 128; idx += THREADS)
        smf[OFF_W3 + (idx >> 7) * 132 + (idx & 127)] = w3[idx];
    for (int idx = tid; idx < 5 * 128; idx += THREADS) {
        int np = idx >> 7, r = idx & 127;
        int i = r >> 1, e = r & 1;
        smf[OFF_W4 + np * 132 + 2 * i + e] = w4[(2 * np + e) * 64 + i];
    }

    // ---- roles ----
    // L1/L2: warp tile = 16 neurons x 32 pairs. Thread: 4 neurons x 4 pairs.
    const int ng  = lane & 3;   // neuron group: j = 16*warp + ng + 4u
    const int pgk = lane >> 2;  // pair group:   p = pgk + 8v
    // L3: warp tile = 8 neurons x 32 pairs. Thread: 4 neurons x 2 pairs.
    const int ng3 = lane & 1;   // j3 = 8*warp + ng3 + 2u
    const int pg3 = lane >> 1;  // p  = pg3 + 16v
    // L4: tid<160: np4 = warp (0..4) -> neurons {2np4, 2np4+1}; pair = lane (0..31)
    const int np4 = warp;

    const float* w1r[4];
    const float* w2r[4];
    const float* w3r[4];
#pragma unroll
    for (int u = 0; u < 4; u++) {
        int j12 = 16 * warp + ng + 4 * u;
        w1r[u] = smf + OFF_W1 + j12 * 20;
        w2r[u] = smf + OFF_W2 + j12 * 132;
        w3r[u] = smf + OFF_W3 + (8 * warp + ng3 + 2 * u) * 132;
    }
    const u64* xr[4];
    const u64* s1r[4];
#pragma unroll
    for (int v = 0; v < 4; v++) {
        xr[v]  = smu + OFF_XP / 2 + (pgk + 8 * v) * 18;
        s1r[v] = smu + OFF_S1 / 2 + (pgk + 8 * v) * 130;
    }
    const u64* s2r[2];
#pragma unroll
    for (int v = 0; v < 2; v++)
        s2r[v] = smu + OFF_S2 / 2 + (pg3 + 16 * v) * 130;

    const u64* w4p = smu + OFF_W4 / 2 + np4 * 66;
    const u64* s3a = smu + OFF_S3 / 2 + lane * 66;   // one batch-pair per L4 thread

    u64* s1w = smu + OFF_S1 / 2;
    u64* s2w = smu + OFF_S2 / 2;
    u64* s3w = smu + OFF_S3 / 2;

    // ---- membrane state ----
    u64 mem1[4][4], mem2[4][4], mem3[4][2], mem4[2];
#pragma unroll
    for (int u = 0; u < 4; u++)
#pragma unroll
        for (int v = 0; v < 4; v++) { mem1[u][v] = 0ull; mem2[u][v] = 0ull; }
#pragma unroll
    for (int u = 0; u < 4; u++) { mem3[u][0] = 0ull; mem3[u][1] = 0ull; }
    mem4[0] = 0ull; mem4[1] = 0ull;

    __syncthreads();

    for (int t = 0; t < T_STEPS; t++) {
        // ---- stage x: 64 batches x 16 feats, packed by batch pair ----
        const float* xg = x + ((size_t)t * (size_t)Btot + (size_t)b0) * 16;
#pragma unroll
        for (int r = 0; r < 4; r++) {
            int idx = tid + r * 256;
            int b = idx >> 4, f = idx & 15;
            smf[OFF_XP + (b >> 1) * 36 + 2 * f + (b & 1)] = xg[idx];
        }
        __syncthreads();

        // ---- layer 1: K=16 ----
        {
            u64 acc[4][4];
#pragma unroll
            for (int u = 0; u < 4; u++)
#pragma unroll
                for (int v = 0; v < 4; v++) acc[u][v] = 0ull;
#pragma unroll
            for (int f = 0; f < 16; f += 4) {
                u64 wd[4][4];
#pragma unroll
                for (int u = 0; u < 4; u++) {
                    float4 w = *(const float4*)(w1r[u] + f);
                    wd[u][0] = dup2(w.x); wd[u][1] = dup2(w.y);
                    wd[u][2] = dup2(w.z); wd[u][3] = dup2(w.w);
                }
#pragma unroll
                for (int v = 0; v < 4; v++) {
                    ulonglong2 xA = *(const ulonglong2*)(xr[v] + f);
                    ulonglong2 xB = *(const ulonglong2*)(xr[v] + f + 2);
#pragma unroll
                    for (int u = 0; u < 4; u++) {
                        fma2(acc[u][v], xA.x, wd[u][0]);
                        fma2(acc[u][v], xA.y, wd[u][1]);
                        fma2(acc[u][v], xB.x, wd[u][2]);
                        fma2(acc[u][v], xB.y, wd[u][3]);
                    }
                }
            }
#pragma unroll
            for (int u = 0; u < 4; u++) {
                int j = 16 * warp + ng + 4 * u;
#pragma unroll
                for (int v = 0; v < 4; v++) {
                    int p = pgk + 8 * v;
                    s1w[p * 130 + j] = lif2(mem1[u][v], acc[u][v]);
                }
            }
        }
        __syncthreads();

        // ---- layer 2: K=128 ----
        {
            u64 acc[4][4];
#pragma unroll
            for (int u = 0; u < 4; u++)
#pragma unroll
                for (int v = 0; v < 4; v++) acc[u][v] = 0ull;
#pragma unroll 2
            for (int i = 0; i < 128; i += 4) {
                u64 wd[4][4];
#pragma unroll
                for (int u = 0; u < 4; u++) {
                    float4 w = *(const float4*)(w2r[u] + i);
                    wd[u][0] = dup2(w.x); wd[u][1] = dup2(w.y);
                    wd[u][2] = dup2(w.z); wd[u][3] = dup2(w.w);
                }
#pragma unroll
                for (int v = 0; v < 4; v++) {
                    ulonglong2 sA = *(const ulonglong2*)(s1r[v] + i);
                    ulonglong2 sB = *(const ulonglong2*)(s1r[v] + i + 2);
#pragma unroll
                    for (int u = 0; u < 4; u++) {
                        fma2(acc[u][v], sA.x, wd[u][0]);
                        fma2(acc[u][v], sA.y, wd[u][1]);
                        fma2(acc[u][v], sB.x, wd[u][2]);
                        fma2(acc[u][v], sB.y, wd[u][3]);
                    }
                }
            }
#pragma unroll
            for (int u = 0; u < 4; u++) {
                int j = 16 * warp + ng + 4 * u;
#pragma unroll
                for (int v = 0; v < 4; v++) {
                    int p = pgk + 8 * v;
                    s2w[p * 130 + j] = lif2(mem2[u][v], acc[u][v]);
                }
            }
        }
        __syncthreads();

        // ---- layer 3: K=128, 64 neurons ----
        {
            u64 acc[4][2];
#pragma unroll
            for (int u = 0; u < 4; u++) { acc[u][0] = 0ull; acc[u][1] = 0ull; }
#pragma unroll 2
            for (int i = 0; i < 128; i += 4) {
                u64 wd[4][4];
#pragma unroll
                for (int u = 0; u < 4; u++) {
                    float4 w = *(const float4*)(w3r[u] + i);
                    wd[u][0] = dup2(w.x); wd[u][1] = dup2(w.y);
                    wd[u][2] = dup2(w.z); wd[u][3] = dup2(w.w);
                }
#pragma unroll
                for (int v = 0; v < 2; v++) {
                    ulonglong2 sA = *(const ulonglong2*)(s2r[v] + i);
                    ulonglong2 sB = *(const ulonglong2*)(s2r[v] + i + 2);
#pragma unroll
                    for (int u = 0; u < 4; u++) {
                        fma2(acc[u][v], sA.x, wd[u][0]);
                        fma2(acc[u][v], sA.y, wd[u][1]);
                        fma2(acc[u][v], sB.x, wd[u][2]);
                        fma2(acc[u][v], sB.y, wd[u][3]);
                    }
                }
            }
#pragma unroll
            for (int u = 0; u < 4; u++) {
                int n = 8 * warp + ng3 + 2 * u;
#pragma unroll
                for (int v = 0; v < 2; v++) {
                    int p = pg3 + 16 * v;
                    s3w[p * 66 + n] = lif2(mem3[u][v], acc[u][v]);
                }
            }
        }
        __syncthreads();

        // ---- layer 4: K=64, 10 neurons, 1 batch-pair per thread (32 pairs x 5 warps) ----
        if (tid < 160) {
            u64 a0 = 0ull, a1 = 0ull;
#pragma unroll 4
            for (int i = 0; i < 64; i += 2) {
                ulonglong2 wp = *(const ulonglong2*)(w4p + i);   // {w(n0,i),w(n1,i)},{w(n0,i+1),w(n1,i+1)}
                ulonglong2 sp = *(const ulonglong2*)(s3a + i);   // {s(b0,i),s(b1,i)},{...,i+1}
                float lo, hi;
                unpack2(sp.x, lo, hi);
                fma2(a0, dup2(lo), wp.x); fma2(a1, dup2(hi), wp.x);
                unpack2(sp.y, lo, hi);
                fma2(a0, dup2(lo), wp.y); fma2(a1, dup2(hi), wp.y);
            }
            u64 sp0 = lif2(mem4[0], a0);   // neurons (2np4,2np4+1) @ batch b0+2*lane
            u64 sp1 = lif2(mem4[1], a1);   // @ batch b0+2*lane+1
            size_t ob = ((size_t)t * (size_t)Btot + (size_t)(b0 + 2 * lane)) * 10 + 2 * np4;
            *reinterpret_cast<u64*>(out + ob)      = sp0;
            *reinterpret_cast<u64*>(out + ob + 10) = sp1;
        }
        __syncthreads();
    }
}

extern "C" void kernel_launch(void* const* d_in, const int* in_sizes, int n_in,
                              void* d_out, int out_size) {
    const float* x  = (const float*)d_in[0];
    const float* w1 = (const float*)d_in[1];
    const float* w2 = (const float*)d_in[2];
    const float* w3 = (const float*)d_in[3];
    const float* w4 = (const float*)d_in[4];
    float* out = (float*)d_out;

    const int Btot = in_sizes[0] / (T_STEPS * 16);  // 65536
    const int grid = Btot / 64;                     // 1024

    cudaFuncSetAttribute(snn_kernel,
                         cudaFuncAttributeMaxDynamicSharedMemorySize,
                         SMEM_BYTES);
    snn_kernel<<<grid, THREADS, SMEM_BYTES>>>(x, w1, w2, w3, w4, out, Btot);
}

// round 5
// speedup vs baseline: 1.9969x; 1.0285x over previous
#include <cuda_runtime.h>

#define THREADS 512
#define T_STEPS 20
#define BETA 0.9f
#define THR 1.0f

typedef unsigned long long u64;

// ---- smem layout (float offsets) ---- (identical to R4)
#define OFF_W1 0
#define OFF_W2 2560
#define OFF_W3 19456
#define OFF_W4 27904
#define OFF_XP 28564
#define OFF_S1 29716
#define OFF_S2 38036
#define OFF_S3 46356
#define SMEM_FLOATS 50580
#define SMEM_BYTES (SMEM_FLOATS * 4)   // 202320 B

// ---- packed fp32 helpers ----
__device__ __forceinline__ u64 dup2(float w) {
    u64 r; asm("mov.b64 %0, {%1, %1};" : "=l"(r) : "f"(w)); return r;
}
__device__ __forceinline__ void fma2(u64 &d, u64 a, u64 b) {
    asm("fma.rn.f32x2 %0, %1, %2, %0;" : "+l"(d) : "l"(a), "l"(b));
}
__device__ __forceinline__ void unpack2(u64 v, float &lo, float &hi) {
    asm("mov.b64 {%0, %1}, %2;" : "=f"(lo), "=f"(hi) : "l"(v));
}
__device__ __forceinline__ u64 pack2(float lo, float hi) {
    u64 r; asm("mov.b64 %0, {%1, %2};" : "=l"(r) : "f"(lo), "f"(hi)); return r;
}
__device__ __forceinline__ u64 lif2(u64 &mem, u64 cur) {
    float m0, m1, c0, c1;
    unpack2(mem, m0, m1);
    unpack2(cur, c0, c1);
    float r0 = (m0 > THR) ? 1.0f : 0.0f;
    float r1 = (m1 > THR) ? 1.0f : 0.0f;
    m0 = fmaf(BETA, m0, c0) - r0;
    m1 = fmaf(BETA, m1, c1) - r1;
    float s0 = (m0 > THR) ? 1.0f : 0.0f;
    float s1 = (m1 > THR) ? 1.0f : 0.0f;
    mem = pack2(m0, m1);
    return pack2(s0, s1);
}

__global__ void __launch_bounds__(THREADS, 1)
snn_kernel(const float* __restrict__ x,
           const float* __restrict__ w1,
           const float* __restrict__ w2,
           const float* __restrict__ w3,
           const float* __restrict__ w4,
           float* __restrict__ out,
           int Btot)
{
    extern __shared__ float smf[];
    u64* smu = reinterpret_cast<u64*>(smf);

    const int tid  = threadIdx.x;
    const int warp = tid >> 5;
    const int lane = tid & 31;
    const int b0   = blockIdx.x * 64;

    // ---- stage weights ----
    for (int idx = tid; idx < 128 * 16; idx += THREADS)
        smf[OFF_W1 + (idx >> 4) * 20 + (idx & 15)] = w1[idx];
    for (int idx = tid; idx < 128 * 128; idx += THREADS)
        smf[OFF_W2 + (idx >> 7) * 132 + (idx & 127)] = w2[idx];
    for (int idx = tid; idx < 64 * 128; idx += THREADS)
        smf[OFF_W3 + (idx >> 7) * 132 + (idx & 127)] = w3[idx];
    for (int idx = tid; idx < 5 * 128; idx += THREADS) {
        int np = idx >> 7, r = idx & 127;
        int i = r >> 1, e = r & 1;
        smf[OFF_W4 + np * 132 + 2 * i + e] = w4[(2 * np + e) * 64 + i];
    }

    // ---- roles (16 warps) ----
    // L1/L2: warp tile = 8 neurons x 32 pairs. Thread: 4 neurons x 2 pairs.
    //   j = 8*warp + ng + 2u (u<4), p = pg + 16v (v<2)
    const int ng  = lane & 1;
    const int pg  = lane >> 1;
    // L3: warp tile = 4 neurons x 32 pairs. Thread: 2 neurons x 2 pairs.
    //   j3 = 4*warp + ng3 + 2u (u<2), p = pg3 + 16v (v<2)
    const int ng3 = lane & 1;
    const int pg3 = lane >> 1;
    // L4: tid<160: np4 = warp (0..4) -> neurons {2np4,2np4+1}; pair = lane
    const int np4 = warp;

    const float* w1r[4];
    const float* w2r[4];
    const float* w3r[2];
#pragma unroll
    for (int u = 0; u < 4; u++) {
        int j12 = 8 * warp + ng + 2 * u;
        w1r[u] = smf + OFF_W1 + j12 * 20;
        w2r[u] = smf + OFF_W2 + j12 * 132;
    }
#pragma unroll
    for (int u = 0; u < 2; u++)
        w3r[u] = smf + OFF_W3 + (4 * warp + ng3 + 2 * u) * 132;

    const u64* xr[2];
    const u64* s1r[2];
    const u64* s2r[2];
#pragma unroll
    for (int v = 0; v < 2; v++) {
        xr[v]  = smu + OFF_XP / 2 + (pg + 16 * v) * 18;
        s1r[v] = smu + OFF_S1 / 2 + (pg + 16 * v) * 130;
        s2r[v] = smu + OFF_S2 / 2 + (pg3 + 16 * v) * 130;
    }

    const u64* w4p = smu + OFF_W4 / 2 + np4 * 66;
    const u64* s3a = smu + OFF_S3 / 2 + lane * 66;

    u64* s1w = smu + OFF_S1 / 2;
    u64* s2w = smu + OFF_S2 / 2;
    u64* s3w = smu + OFF_S3 / 2;

    // ---- membrane state ----
    u64 mem1[4][2], mem2[4][2], mem3[2][2], mem4[2];
#pragma unroll
    for (int u = 0; u < 4; u++)
#pragma unroll
        for (int v = 0; v < 2; v++) { mem1[u][v] = 0ull; mem2[u][v] = 0ull; }
#pragma unroll
    for (int u = 0; u < 2; u++) { mem3[u][0] = 0ull; mem3[u][1] = 0ull; }
    mem4[0] = 0ull; mem4[1] = 0ull;

    __syncthreads();

    for (int t = 0; t < T_STEPS; t++) {
        // ---- stage x: 64 batches x 16 feats, packed by batch pair ----
        const float* xg = x + ((size_t)t * (size_t)Btot + (size_t)b0) * 16;
#pragma unroll
        for (int r = 0; r < 2; r++) {
            int idx = tid + r * THREADS;
            int b = idx >> 4, f = idx & 15;
            smf[OFF_XP + (b >> 1) * 36 + 2 * f + (b & 1)] = xg[idx];
        }
        __syncthreads();

        // ---- layer 1: K=16 ----
        {
            u64 acc[4][2];
#pragma unroll
            for (int u = 0; u < 4; u++) { acc[u][0] = 0ull; acc[u][1] = 0ull; }
#pragma unroll
            for (int f = 0; f < 16; f += 4) {
                u64 wd[4][4];
#pragma unroll
                for (int u = 0; u < 4; u++) {
                    float4 w = *(const float4*)(w1r[u] + f);
                    wd[u][0] = dup2(w.x); wd[u][1] = dup2(w.y);
                    wd[u][2] = dup2(w.z); wd[u][3] = dup2(w.w);
                }
#pragma unroll
                for (int v = 0; v < 2; v++) {
                    ulonglong2 xA = *(const ulonglong2*)(xr[v] + f);
                    ulonglong2 xB = *(const ulonglong2*)(xr[v] + f + 2);
#pragma unroll
                    for (int u = 0; u < 4; u++) {
                        fma2(acc[u][v], xA.x, wd[u][0]);
                        fma2(acc[u][v], xA.y, wd[u][1]);
                        fma2(acc[u][v], xB.x, wd[u][2]);
                        fma2(acc[u][v], xB.y, wd[u][3]);
                    }
                }
            }
#pragma unroll
            for (int u = 0; u < 4; u++) {
                int j = 8 * warp + ng + 2 * u;
#pragma unroll
                for (int v = 0; v < 2; v++) {
                    int p = pg + 16 * v;
                    s1w[p * 130 + j] = lif2(mem1[u][v], acc[u][v]);
                }
            }
        }
        __syncthreads();

        // ---- layer 2: K=128 ----
        {
            u64 acc[4][2];
#pragma unroll
            for (int u = 0; u < 4; u++) { acc[u][0] = 0ull; acc[u][1] = 0ull; }
#pragma unroll 4
            for (int i = 0; i < 128; i += 4) {
                u64 wd[4][4];
#pragma unroll
                for (int u = 0; u < 4; u++) {
                    float4 w = *(const float4*)(w2r[u] + i);
                    wd[u][0] = dup2(w.x); wd[u][1] = dup2(w.y);
                    wd[u][2] = dup2(w.z); wd[u][3] = dup2(w.w);
                }
#pragma unroll
                for (int v = 0; v < 2; v++) {
                    ulonglong2 sA = *(const ulonglong2*)(s1r[v] + i);
                    ulonglong2 sB = *(const ulonglong2*)(s1r[v] + i + 2);
#pragma unroll
                    for (int u = 0; u < 4; u++) {
                        fma2(acc[u][v], sA.x, wd[u][0]);
                        fma2(acc[u][v], sA.y, wd[u][1]);
                        fma2(acc[u][v], sB.x, wd[u][2]);
                        fma2(acc[u][v], sB.y, wd[u][3]);
                    }
                }
            }
#pragma unroll
            for (int u = 0; u < 4; u++) {
                int j = 8 * warp + ng + 2 * u;
#pragma unroll
                for (int v = 0; v < 2; v++) {
                    int p = pg + 16 * v;
                    s2w[p * 130 + j] = lif2(mem2[u][v], acc[u][v]);
                }
            }
        }
        __syncthreads();

        // ---- layer 3: K=128, 64 neurons ----
        {
            u64 acc[2][2];
            acc[0][0] = acc[0][1] = acc[1][0] = acc[1][1] = 0ull;
#pragma unroll 4
            for (int i = 0; i < 128; i += 4) {
                u64 wd[2][4];
#pragma unroll
                for (int u = 0; u < 2; u++) {
                    float4 w = *(const float4*)(w3r[u] + i);
                    wd[u][0] = dup2(w.x); wd[u][1] = dup2(w.y);
                    wd[u][2] = dup2(w.z); wd[u][3] = dup2(w.w);
                }
#pragma unroll
                for (int v = 0; v < 2; v++) {
                    ulonglong2 sA = *(const ulonglong2*)(s2r[v] + i);
                    ulonglong2 sB = *(const ulonglong2*)(s2r[v] + i + 2);
#pragma unroll
                    for (int u = 0; u < 2; u++) {
                        fma2(acc[u][v], sA.x, wd[u][0]);
                        fma2(acc[u][v], sA.y, wd[u][1]);
                        fma2(acc[u][v], sB.x, wd[u][2]);
                        fma2(acc[u][v], sB.y, wd[u][3]);
                    }
                }
            }
#pragma unroll
            for (int u = 0; u < 2; u++) {
                int n = 4 * warp + ng3 + 2 * u;
#pragma unroll
                for (int v = 0; v < 2; v++) {
                    int p = pg3 + 16 * v;
                    s3w[p * 66 + n] = lif2(mem3[u][v], acc[u][v]);
                }
            }
        }
        __syncthreads();

        // ---- layer 4: K=64, 10 neurons, 1 batch-pair per thread ----
        if (tid < 160) {
            u64 a0 = 0ull, a1 = 0ull;
#pragma unroll 4
            for (int i = 0; i < 64; i += 2) {
                ulonglong2 wp = *(const ulonglong2*)(w4p + i);
                ulonglong2 sp = *(const ulonglong2*)(s3a + i);
                float lo, hi;
                unpack2(sp.x, lo, hi);
                fma2(a0, dup2(lo), wp.x); fma2(a1, dup2(hi), wp.x);
                unpack2(sp.y, lo, hi);
                fma2(a0, dup2(lo), wp.y); fma2(a1, dup2(hi), wp.y);
            }
            u64 sp0 = lif2(mem4[0], a0);
            u64 sp1 = lif2(mem4[1], a1);
            size_t ob = ((size_t)t * (size_t)Btot + (size_t)(b0 + 2 * lane)) * 10 + 2 * np4;
            *reinterpret_cast<u64*>(out + ob)      = sp0;
            *reinterpret_cast<u64*>(out + ob + 10) = sp1;
        }
        __syncthreads();
    }
}

extern "C" void kernel_launch(void* const* d_in, const int* in_sizes, int n_in,
                              void* d_out, int out_size) {
    const float* x  = (const float*)d_in[0];
    const float* w1 = (const float*)d_in[1];
    const float* w2 = (const float*)d_in[2];
    const float* w3 = (const float*)d_in[3];
    const float* w4 = (const float*)d_in[4];
    float* out = (float*)d_out;

    const int Btot = in_sizes[0] / (T_STEPS * 16);  // 65536
    const int grid = Btot / 64;                     // 1024

    cudaFuncSetAttribute(snn_kernel,
                         cudaFuncAttributeMaxDynamicSharedMemorySize,
                         SMEM_BYTES);
    snn_kernel<<<grid, THREADS, SMEM_BYTES>>>(x, w1, w2, w3, w4, out, Btot);
}

// round 7
// speedup vs baseline: 4.4322x; 2.2195x over previous
#include <cuda_runtime.h>
#include <cuda_bf16.h>

#define THREADS 256
#define T_STEPS 20
#define BETA 0.9f
#define THR 1.0f

typedef unsigned int u32;

// ---- smem byte offsets ----
#define SW1 0            // 3 splits x 128 rows x 32B   (w1 [n][k16], pitch 32)
#define SW2 12288        // 3 x 128 x 256B               (w2 [n][k128], pitch 256)
#define SW3 110592       // 3 x 64 x 256B
#define SW4 159744       // 3 x 16 x 128B                (w4 [n pad16][k64], pitch 128)
#define SS1 165888       // 64 x 256B  (s1 spikes bf16, pitch 256)
#define SS2 182272       // 64 x 256B  (s2)
#define SS3 SS1          // 64 x 128B  (s3, aliases s1)
#define SXS SS2          // 3 x 64 x 32B (x splits, aliases s2)
#define SM_TOTAL 198656

__device__ __forceinline__ float bfv(float v) { return __bfloat162float(__float2bfloat16(v)); }

__device__ __forceinline__ void ldsm4(u32 a[4], u32 addr) {
    asm volatile("ldmatrix.sync.aligned.m8n8.x4.shared.b16 {%0,%1,%2,%3}, [%4];"
        : "=r"(a[0]), "=r"(a[1]), "=r"(a[2]), "=r"(a[3]) : "r"(addr));
}
__device__ __forceinline__ void ldsm2(u32 &r0, u32 &r1, u32 addr) {
    asm volatile("ldmatrix.sync.aligned.m8n8.x2.shared.b16 {%0,%1}, [%2];"
        : "=r"(r0), "=r"(r1) : "r"(addr));
}
__device__ __forceinline__ void mma_bf16(float d[4], const u32 a[4], u32 b0, u32 b1) {
    asm volatile("mma.sync.aligned.m16n8k16.row.col.f32.bf16.bf16.f32 "
        "{%0,%1,%2,%3}, {%4,%5,%6,%7}, {%8,%9}, {%0,%1,%2,%3};"
        : "+f"(d[0]), "+f"(d[1]), "+f"(d[2]), "+f"(d[3])
        : "r"(a[0]), "r"(a[1]), "r"(a[2]), "r"(a[3]), "r"(b0), "r"(b1));
}
__device__ __forceinline__ void sts32(u32 addr, u32 v) {
    asm volatile("st.shared.b32 [%0], %1;" :: "r"(addr), "r"(v) : "memory");
}

// LIF on 4 accumulator elems of one C block; returns packed bf16 spike pairs
// p0 = spikes (row r: cols 2c,2c+1), p1 = (row r+8)
__device__ __forceinline__ void lif4(float* mem, const float* d, u32 &p0, u32 &p1) {
    float s[4];
#pragma unroll
    for (int e = 0; e < 4; e++) {
        float m = mem[e];
        float reset = (m > THR) ? 1.0f : 0.0f;
        m = fmaf(BETA, m, d[e]) - reset;
        mem[e] = m;
        s[e] = (m > THR) ? 1.0f : 0.0f;
    }
    p0 = (s[0] != 0.0f ? 0x3F80u : 0u) | (s[1] != 0.0f ? 0x3F800000u : 0u);
    p1 = (s[2] != 0.0f ? 0x3F80u : 0u) | (s[3] != 0.0f ? 0x3F800000u : 0u);
}

__global__ void __launch_bounds__(THREADS, 1)
snn_mma_kernel(const float* __restrict__ x,
               const float* __restrict__ w1g,
               const float* __restrict__ w2g,
               const float* __restrict__ w3g,
               const float* __restrict__ w4g,
               float* __restrict__ out,
               int Btot)
{
    extern __shared__ char sm[];
    u32 smb;
    asm("{ .reg .u64 t; cvta.to.shared.u64 t, %1; cvt.u32.u64 %0, t; }"
        : "=r"(smb) : "l"(sm));

    const int tid  = threadIdx.x;
    const int w    = tid >> 5;
    const int lane = tid & 31;
    const int b0   = blockIdx.x * 64;

    // ---- stage weights: 3-way exact bf16 split + XOR swizzle ----
    for (int idx = tid; idx < 128 * 128; idx += THREADS) {
        int n = idx >> 7, k = idx & 127;
        float v = w2g[idx];
        float r1_ = v - bfv(v);
        float r2_ = r1_ - bfv(r1_);
        u32 off = (u32)(n * 256 + (((k >> 3) ^ (n & 7)) << 4) + (k & 7) * 2);
        *(__nv_bfloat16*)(sm + SW2 +     0 + off) = __float2bfloat16(v);
        *(__nv_bfloat16*)(sm + SW2 + 32768 + off) = __float2bfloat16(r1_);
        *(__nv_bfloat16*)(sm + SW2 + 65536 + off) = __float2bfloat16(r2_);
    }
    for (int idx = tid; idx < 64 * 128; idx += THREADS) {
        int n = idx >> 7, k = idx & 127;
        float v = w3g[idx];
        float r1_ = v - bfv(v);
        float r2_ = r1_ - bfv(r1_);
        u32 off = (u32)(n * 256 + (((k >> 3) ^ (n & 7)) << 4) + (k & 7) * 2);
        *(__nv_bfloat16*)(sm + SW3 +     0 + off) = __float2bfloat16(v);
        *(__nv_bfloat16*)(sm + SW3 + 16384 + off) = __float2bfloat16(r1_);
        *(__nv_bfloat16*)(sm + SW3 + 32768 + off) = __float2bfloat16(r2_);
    }
    for (int idx = tid; idx < 128 * 16; idx += THREADS) {
        int n = idx >> 4, k = idx & 15;
        float v = w1g[idx];
        float r1_ = v - bfv(v);
        float r2_ = r1_ - bfv(r1_);
        u32 off = (u32)(n * 32 + (((k >> 3) ^ (n & 1)) << 4) + (k & 7) * 2);
        *(__nv_bfloat16*)(sm + SW1 +    0 + off) = __float2bfloat16(v);
        *(__nv_bfloat16*)(sm + SW1 + 4096 + off) = __float2bfloat16(r1_);
        *(__nv_bfloat16*)(sm + SW1 + 8192 + off) = __float2bfloat16(r2_);
    }
    for (int idx = tid; idx < 16 * 64; idx += THREADS) {
        int n = idx >> 6, k = idx & 63;
        float v = (n < 10) ? w4g[n * 64 + k] : 0.0f;
        float r1_ = v - bfv(v);
        float r2_ = r1_ - bfv(r1_);
        u32 off = (u32)(n * 128 + (((k >> 3) ^ (n & 7)) << 4) + (k & 7) * 2);
        *(__nv_bfloat16*)(sm + SW4 +    0 + off) = __float2bfloat16(v);
        *(__nv_bfloat16*)(sm + SW4 + 2048 + off) = __float2bfloat16(r1_);
        *(__nv_bfloat16*)(sm + SW4 + 4096 + off) = __float2bfloat16(r2_);
    }

    // ---- lane roles (ldmatrix fragment addressing) ----
    const int arow = ((lane >> 3) & 1) * 8 + (lane & 7); // A-source row within 16
    const int ac   = lane >> 4;                          // A chunk half (0/1)
    const int brow = ((lane >> 4) << 3) + (lane & 7);    // B-source n-row within 16
    const int badd = (lane >> 3) & 1;                    // B chunk half
    const int r_   = lane >> 2;                          // C row 0..7
    const int c_   = lane & 3;                           // C col pair 0..3
    const u32 rx8  = (u32)(lane & 7) << 4;               // swizzle key for pitch 256/128

    // ---- membranes ----
    float m1[32], m2[32], m3[16], m4[4];
#pragma unroll
    for (int i = 0; i < 32; i++) { m1[i] = 0.f; m2[i] = 0.f; }
#pragma unroll
    for (int i = 0; i < 16; i++) m3[i] = 0.f;
#pragma unroll
    for (int i = 0; i < 4; i++)  m4[i] = 0.f;

    const int np3 = w & 3,  bh  = w >> 2;   // L3 role
    const int Mw  = w >> 1, nb4 = w & 1;    // L4 role

    __syncthreads();

    for (int t = 0; t < T_STEPS; t++) {
        // ===== stage x splits (64 b x 16 f, 3 levels, pitch 32, swizzle b&1) =====
        {
            int b = tid >> 2, f4 = (tid & 3) << 2;
            float4 v = *(const float4*)(x + ((size_t)t * (size_t)Btot + (size_t)(b0 + b)) * 16 + f4);
            float h0 = bfv(v.x), h1 = bfv(v.y), h2 = bfv(v.z), h3 = bfv(v.w);
            float e0 = v.x - h0, e1 = v.y - h1, e2 = v.z - h2, e3 = v.w - h3;
            float g0 = bfv(e0), g1 = bfv(e1), g2 = bfv(e2), g3 = bfv(e3);
            float f0 = e0 - g0, f1 = e1 - g1, f2 = e2 - g2, f3 = e3 - g3;
            u32 base = smb + SXS + (u32)(b * 32 + (((f4 >> 3) ^ (b & 1)) << 4) + (f4 & 7) * 2);
            u32 p;
            p = ((u32)__bfloat16_as_ushort(__float2bfloat16(v.x))) | ((u32)__bfloat16_as_ushort(__float2bfloat16(v.y)) << 16);
            sts32(base, p);
            p = ((u32)__bfloat16_as_ushort(__float2bfloat16(v.z))) | ((u32)__bfloat16_as_ushort(__float2bfloat16(v.w)) << 16);
            sts32(base + 4, p);
            p = ((u32)__bfloat16_as_ushort(__float2bfloat16(e0))) | ((u32)__bfloat16_as_ushort(__float2bfloat16(e1)) << 16);
            sts32(base + 2048, p);
            p = ((u32)__bfloat16_as_ushort(__float2bfloat16(e2))) | ((u32)__bfloat16_as_ushort(__float2bfloat16(e3)) << 16);
            sts32(base + 2048 + 4, p);
            p = ((u32)__bfloat16_as_ushort(__float2bfloat16(f0))) | ((u32)__bfloat16_as_ushort(__float2bfloat16(f1)) << 16);
            sts32(base + 4096, p);
            p = ((u32)__bfloat16_as_ushort(__float2bfloat16(f2))) | ((u32)__bfloat16_as_ushort(__float2bfloat16(f3)) << 16);
            sts32(base + 4096 + 4, p);
        }
        __syncthreads();

        // ===== L1: N=128 (warp np=w), K=16, 6 split terms =====
        {
            u32 bw[3][4];
#pragma unroll
            for (int lv = 0; lv < 3; lv++)
                ldsm4(bw[lv], smb + SW1 + (u32)(lv * 4096 + (16 * w + brow) * 32)
                              + (((u32)badd << 4) ^ ((u32)(brow & 1) << 4)));
            float acc[32];
#pragma unroll
            for (int i = 0; i < 32; i++) acc[i] = 0.f;
#pragma unroll
            for (int M = 0; M < 4; M++) {
                u32 ax[3][4];
#pragma unroll
                for (int lv = 0; lv < 3; lv++)
                    ldsm4(ax[lv], smb + SXS + (u32)(lv * 2048 + (16 * M + arow) * 32)
                                  + (((u32)ac << 4) ^ ((u32)(arow & 1) << 4)));
                const int la[6] = {0, 0, 1, 0, 1, 2};
                const int lb[6] = {0, 1, 0, 2, 1, 0};
#pragma unroll
                for (int s = 0; s < 6; s++) {
                    mma_bf16(&acc[(M * 2 + 0) * 4], ax[la[s]], bw[lb[s]][0], bw[lb[s]][1]);
                    mma_bf16(&acc[(M * 2 + 1) * 4], ax[la[s]], bw[lb[s]][2], bw[lb[s]][3]);
                }
            }
            // epilogue -> s1
#pragma unroll
            for (int M = 0; M < 4; M++)
#pragma unroll
                for (int nb = 0; nb < 2; nb++) {
                    u32 p0, p1;
                    lif4(&m1[(M * 2 + nb) * 4], &acc[(M * 2 + nb) * 4], p0, p1);
                    u32 a0 = smb + SS1 + (u32)((16 * M + r_) * 256)
                             + (((u32)(2 * w + nb) << 4) ^ ((u32)r_ << 4)) + 4 * c_;
                    sts32(a0, p0);
                    sts32(a0 + 8 * 256, p1);
                }
        }
        __syncthreads();

        // ===== L2: N=128 (warp np=w), K=128, 3 splits =====
        {
            float acc[32];
#pragma unroll
            for (int i = 0; i < 32; i++) acc[i] = 0.f;
#pragma unroll
            for (int kc = 0; kc < 8; kc++) {
                u32 a_[4][4];
#pragma unroll
                for (int M = 0; M < 4; M++)
                    ldsm4(a_[M], smb + SS1 + (u32)((16 * M + arow) * 256)
                                 + (((u32)(2 * kc + ac) << 4) ^ rx8));
#pragma unroll
                for (int s = 0; s < 3; s++) {
                    u32 b_[4];
                    ldsm4(b_, smb + SW2 + (u32)(s * 32768 + (16 * w + brow) * 256)
                              + (((u32)(2 * kc + badd) << 4) ^ rx8));
#pragma unroll
                    for (int M = 0; M < 4; M++) {
                        mma_bf16(&acc[(M * 2 + 0) * 4], a_[M], b_[0], b_[1]);
                        mma_bf16(&acc[(M * 2 + 1) * 4], a_[M], b_[2], b_[3]);
                    }
                }
            }
#pragma unroll
            for (int M = 0; M < 4; M++)
#pragma unroll
                for (int nb = 0; nb < 2; nb++) {
                    u32 p0, p1;
                    lif4(&m2[(M * 2 + nb) * 4], &acc[(M * 2 + nb) * 4], p0, p1);
                    u32 a0 = smb + SS2 + (u32)((16 * M + r_) * 256)
                             + (((u32)(2 * w + nb) << 4) ^ ((u32)r_ << 4)) + 4 * c_;
                    sts32(a0, p0);
                    sts32(a0 + 8 * 256, p1);
                }
        }
        __syncthreads();

        // ===== L3: N=64 (warp np3, batch-half bh), K=128 =====
        {
            float acc[16];
#pragma unroll
            for (int i = 0; i < 16; i++) acc[i] = 0.f;
#pragma unroll
            for (int kc = 0; kc < 8; kc++) {
                u32 a_[2][4];
#pragma unroll
                for (int M = 0; M < 2; M++)
                    ldsm4(a_[M], smb + SS2 + (u32)((32 * bh + 16 * M + arow) * 256)
                                 + (((u32)(2 * kc + ac) << 4) ^ rx8));
#pragma unroll
                for (int s = 0; s < 3; s++) {
                    u32 b_[4];
                    ldsm4(b_, smb + SW3 + (u32)(s * 16384 + (16 * np3 + brow) * 256)
                              + (((u32)(2 * kc + badd) << 4) ^ rx8));
#pragma unroll
                    for (int M = 0; M < 2; M++) {
                        mma_bf16(&acc[(M * 2 + 0) * 4], a_[M], b_[0], b_[1]);
                        mma_bf16(&acc[(M * 2 + 1) * 4], a_[M], b_[2], b_[3]);
                    }
                }
            }
#pragma unroll
            for (int M = 0; M < 2; M++)
#pragma unroll
                for (int nb = 0; nb < 2; nb++) {
                    u32 p0, p1;
                    lif4(&m3[(M * 2 + nb) * 4], &acc[(M * 2 + nb) * 4], p0, p1);
                    u32 a0 = smb + SS3 + (u32)((32 * bh + 16 * M + r_) * 128)
                             + (((u32)(2 * np3 + nb) << 4) ^ ((u32)r_ << 4)) + 4 * c_;
                    sts32(a0, p0);
                    sts32(a0 + 8 * 128, p1);
                }
        }
        __syncthreads();

        // ===== L4: N=16(10 real) (warp: M=Mw, n-block=nb4), K=64 =====
        {
            float acc[4] = {0.f, 0.f, 0.f, 0.f};
#pragma unroll
            for (int kc = 0; kc < 4; kc++) {
                u32 a_[4];
                ldsm4(a_, smb + SS3 + (u32)((16 * Mw + arow) * 128)
                          + (((u32)(2 * kc + ac) << 4) ^ rx8));
#pragma unroll
                for (int s = 0; s < 3; s++) {
                    u32 b0, b1;
                    ldsm2(b0, b1, smb + SW4 + (u32)(s * 2048 + (8 * nb4 + (lane & 7)) * 128)
                                  + (((u32)(2 * kc + badd) << 4) ^ ((u32)(lane & 7) << 4)));
                    mma_bf16(acc, a_, b0, b1);
                }
            }
            float s4[4];
#pragma unroll
            for (int e = 0; e < 4; e++) {
                float m = m4[e];
                float reset = (m > THR) ? 1.0f : 0.0f;
                m = fmaf(BETA, m, acc[e]) - reset;
                m4[e] = m;
                s4[e] = (m > THR) ? 1.0f : 0.0f;
            }
            size_t row0 = (size_t)t * (size_t)Btot + (size_t)(b0 + 16 * Mw + r_);
            if (nb4 == 0) {
                *(float2*)(out + row0 * 10 + 2 * c_)       = make_float2(s4[0], s4[1]);
                *(float2*)(out + (row0 + 8) * 10 + 2 * c_) = make_float2(s4[2], s4[3]);
            } else if (c_ == 0) {
                *(float2*)(out + row0 * 10 + 8)       = make_float2(s4[0], s4[1]);
                *(float2*)(out + (row0 + 8) * 10 + 8) = make_float2(s4[2], s4[3]);
            }
        }
        __syncthreads();
    }
}

extern "C" void kernel_launch(void* const* d_in, const int* in_sizes, int n_in,
                              void* d_out, int out_size) {
    const float* x  = (const float*)d_in[0];
    const float* w1 = (const float*)d_in[1];
    const float* w2 = (const float*)d_in[2];
    const float* w3 = (const float*)d_in[3];
    const float* w4 = (const float*)d_in[4];
    float* out = (float*)d_out;

    const int Btot = in_sizes[0] / (T_STEPS * 16);  // 65536
    const int grid = Btot / 64;                     // 1024

    cudaFuncSetAttribute(snn_mma_kernel,
                         cudaFuncAttributeMaxDynamicSharedMemorySize,
                         SM_TOTAL);
    snn_mma_kernel<<<grid, THREADS, SM_TOTAL>>>(x, w1, w2, w3, w4, out, Btot);
}